// round 1
// baseline (speedup 1.0000x reference)
#include <cuda_runtime.h>
#include <math.h>

// Problem constants
#define Bv      2
#define Tv      2048
#define NTOK    (Bv * Tv)      // 4096
#define Dv      512
#define Hv      8
#define HDv     64             // head dim == random-feature dim m
#define FFNv    2048
#define VOCABv  256
#define Lv      2
#define CHUNK   128
#define NCHUNK  (Tv / CHUNK)   // 16

// -------------------- scratch (device globals; no allocs) --------------------
__device__ float g_x[NTOK * Dv];
__device__ float g_a[NTOK * Dv];
__device__ float g_q[NTOK * Dv];
__device__ float g_k[NTOK * Dv];
__device__ float g_v[NTOK * Dv];
__device__ float g_qf[NTOK * Dv];
__device__ float g_kf[NTOK * Dv];
__device__ float g_h[NTOK * FFNv];
__device__ float g_S[Bv * Hv * NCHUNK * HDv * HDv];  // chunk S sums / exclusive prefixes
__device__ float g_z[Bv * Hv * NCHUNK * HDv];        // chunk z sums / exclusive prefixes

// -------------------- embedding + sinusoidal positions --------------------
__global__ void embed_kernel(const int* __restrict__ tokens,
                             const float* __restrict__ emb) {
    int idx = blockIdx.x * blockDim.x + threadIdx.x;
    if (idx >= NTOK * Dv) return;
    int n = idx >> 9;          // token row (b*T + t)
    int j = idx & 511;         // feature
    int t = n & (Tv - 1);      // position within sequence
    float val;
    const float c = 9.210340371976184f / 256.f;  // ln(10000)/half
    if (j < 256) {
        int tok = tokens[n];
        val = emb[tok * 256 + j];
    } else if (j < 384) {
        int i = j - 256;
        float freq = expf(-(2.f * (float)i) * c);
        val = sinf((float)t * freq);
    } else {
        int i = j - 384;
        float freq = expf(-(2.f * (float)i) * c);
        val = cosf((float)t * freq);
    }
    g_x[idx] = val;
}

// -------------------- SGEMM: C = A[M,K] @ B[K,N] + bias (+gelu) --------------------
// BM=BN=128, BK=8, 256 threads, 8x8 microtile. All dims divisible; no bounds checks.
__global__ void __launch_bounds__(256)
gemm_bias(const float* __restrict__ A, const float* __restrict__ B,
          const float* __restrict__ bias, float* __restrict__ C,
          int M, int N, int K, int act) {
    __shared__ float As[8][128];
    __shared__ float Bs[8][128];
    int tid = threadIdx.x;
    int row0 = blockIdx.y * 128, col0 = blockIdx.x * 128;
    int aRow = tid >> 1, aCol = (tid & 1) * 4;
    int bRow = tid >> 5, bCol = (tid & 31) * 4;
    int ty = tid >> 4, tx = tid & 15;

    float acc[8][8];
#pragma unroll
    for (int i = 0; i < 8; i++)
#pragma unroll
        for (int j = 0; j < 8; j++) acc[i][j] = 0.f;

    const float* Aptr = A + (size_t)(row0 + aRow) * K + aCol;
    const float* Bptr = B + (size_t)bRow * N + col0 + bCol;

    for (int k0 = 0; k0 < K; k0 += 8) {
        float4 av = *(const float4*)(Aptr + k0);
        float4 bv = *(const float4*)(Bptr + (size_t)k0 * N);
        As[aCol + 0][aRow] = av.x;
        As[aCol + 1][aRow] = av.y;
        As[aCol + 2][aRow] = av.z;
        As[aCol + 3][aRow] = av.w;
        *(float4*)&Bs[bRow][bCol] = bv;
        __syncthreads();
#pragma unroll
        for (int kk = 0; kk < 8; kk++) {
            float4 a0 = *(const float4*)&As[kk][ty * 8];
            float4 a1 = *(const float4*)&As[kk][ty * 8 + 4];
            float4 b0 = *(const float4*)&Bs[kk][tx * 8];
            float4 b1 = *(const float4*)&Bs[kk][tx * 8 + 4];
            float ar[8] = {a0.x, a0.y, a0.z, a0.w, a1.x, a1.y, a1.z, a1.w};
            float br[8] = {b0.x, b0.y, b0.z, b0.w, b1.x, b1.y, b1.z, b1.w};
#pragma unroll
            for (int i = 0; i < 8; i++)
#pragma unroll
                for (int j = 0; j < 8; j++) acc[i][j] += ar[i] * br[j];
        }
        __syncthreads();
    }

#pragma unroll
    for (int i = 0; i < 8; i++) {
        int r = row0 + ty * 8 + i;
#pragma unroll
        for (int j = 0; j < 8; j++) {
            int cidx = col0 + tx * 8 + j;
            float v = acc[i][j] + bias[cidx];
            if (act == 1) {  // exact gelu
                v = 0.5f * v * (1.f + erff(v * 0.7071067811865475f));
            }
            C[(size_t)r * N + cidx] = v;
        }
    }
}

// -------------------- FAVOR+ feature map (q and k together) --------------------
// qf = exp(xp @ rfs - 0.5*||xp||^2), xp = q * HD^{-1/4}
__global__ void __launch_bounds__(64)
favor_feat(const float* __restrict__ rfs) {
    int gid = blockIdx.x;
    int h = gid % Hv;
    int n = gid / Hv;
    int tid = threadIdx.x;
    int lane = tid & 31, w = tid >> 5;
    __shared__ float sxq[64], sxk[64], sred[4];
    const float sc = 0.3535533905932738f;  // 64^{-1/4}
    int base = n * Dv + h * HDv;
    float qv = g_q[base + tid] * sc;
    float kv = g_k[base + tid] * sc;
    sxq[tid] = qv;
    sxk[tid] = kv;
    float pq = qv * qv, pk = kv * kv;
#pragma unroll
    for (int off = 16; off; off >>= 1) {
        pq += __shfl_down_sync(0xffffffffu, pq, off);
        pk += __shfl_down_sync(0xffffffffu, pk, off);
    }
    if (lane == 0) { sred[w] = pq; sred[2 + w] = pk; }
    __syncthreads();
    float sq2 = sred[0] + sred[1];
    float sk2 = sred[2] + sred[3];
    const float* rf = rfs + h * HDv * HDv + tid;  // column tid of rfs[h]
    float dq = 0.f, dk = 0.f;
#pragma unroll 8
    for (int d = 0; d < HDv; d++) {
        float r = rf[d * HDv];
        dq += sxq[d] * r;
        dk += sxk[d] * r;
    }
    g_qf[base + tid] = expf(dq - 0.5f * sq2);
    g_kf[base + tid] = expf(dk - 0.5f * sk2);
}

// -------------------- phase 1: per-chunk sums of kf (x) v and kf --------------------
__global__ void __launch_bounds__(64)
attn_chunk() {
    int c = blockIdx.x, bh = blockIdx.y;
    int b = bh / Hv, h = bh % Hv;
    int d = threadIdx.x;
    float S[64];
#pragma unroll
    for (int m = 0; m < 64; m++) S[m] = 0.f;
    float z = 0.f;
    __shared__ float sk[64];
    for (int t = c * CHUNK; t < (c + 1) * CHUNK; t++) {
        int base = (b * Tv + t) * Dv + h * HDv;
        sk[d] = g_kf[base + d];
        __syncthreads();
        float vd = g_v[base + d];
        z += sk[d];  // thread d doubles as m=d for z
#pragma unroll
        for (int m = 0; m < 64; m++) S[m] += sk[m] * vd;
        __syncthreads();
    }
    int sb = (bh * NCHUNK + c) * 4096;
#pragma unroll
    for (int m = 0; m < 64; m++) g_S[sb + m * 64 + d] = S[m];
    g_z[(bh * NCHUNK + c) * 64 + d] = z;
}

// -------------------- phase 2: exclusive scan over chunks (in place) --------------------
__global__ void __launch_bounds__(64)
attn_scan() {
    int bh = blockIdx.x, d = threadIdx.x;
    for (int m = 0; m < 64; m++) {
        float acc = 0.f;
        for (int c = 0; c < NCHUNK; c++) {
            int idx = (bh * NCHUNK + c) * 4096 + m * 64 + d;
            float t = g_S[idx];
            g_S[idx] = acc;
            acc += t;
        }
    }
    float za = 0.f;
    for (int c = 0; c < NCHUNK; c++) {
        int idx = (bh * NCHUNK + c) * 64 + d;
        float t = g_z[idx];
        g_z[idx] = za;
        za += t;
    }
}

// -------------------- phase 3: replay chunk with running state, produce attention out ----
__global__ void __launch_bounds__(64)
attn_apply() {
    int c = blockIdx.x, bh = blockIdx.y;
    int b = bh / Hv, h = bh % Hv;
    int d = threadIdx.x;
    int lane = d & 31, w = d >> 5;
    float S[64];
    int sb = (bh * NCHUNK + c) * 4096;
#pragma unroll
    for (int m = 0; m < 64; m++) S[m] = g_S[sb + m * 64 + d];
    float z = g_z[(bh * NCHUNK + c) * 64 + d];
    __shared__ float sk[64], sq[64], sred[2];
    for (int t = c * CHUNK; t < (c + 1) * CHUNK; t++) {
        int base = (b * Tv + t) * Dv + h * HDv;
        sk[d] = g_kf[base + d];
        sq[d] = g_qf[base + d];
        __syncthreads();
        // denominator: den = sum_m qf[m] * zcum[m]  (inclusive)
        z += sk[d];
        float p = sq[d] * z;
#pragma unroll
        for (int off = 16; off; off >>= 1) p += __shfl_down_sync(0xffffffffu, p, off);
        if (lane == 0) sred[w] = p;
        // numerator: S[m][d] += kf[m]*v[d]; num[d] = sum_m qf[m]*S[m][d]
        float vd = g_v[base + d];
        float num = 0.f;
#pragma unroll
        for (int m = 0; m < 64; m++) {
            S[m] += sk[m] * vd;
            num += sq[m] * S[m];
        }
        __syncthreads();
        float den = sred[0] + sred[1];
        g_a[base + d] = num / (den + 1e-16f);
    }
}

// -------------------- LayerNorm + residual add: x += LN(a)*g + b --------------------
__global__ void __launch_bounds__(128)
ln_add(const float* __restrict__ a, const float* __restrict__ g,
       const float* __restrict__ bl, float* __restrict__ x) {
    int n = blockIdx.x, tid = threadIdx.x;
    int lane = tid & 31, w = tid >> 5;
    const float* ar = a + (size_t)n * Dv;
    float v[4];
    float s = 0.f, s2 = 0.f;
#pragma unroll
    for (int i = 0; i < 4; i++) {
        float t = ar[tid + i * 128];
        v[i] = t;
        s += t;
        s2 += t * t;
    }
    __shared__ float sh[8];
#pragma unroll
    for (int off = 16; off; off >>= 1) {
        s += __shfl_down_sync(0xffffffffu, s, off);
        s2 += __shfl_down_sync(0xffffffffu, s2, off);
    }
    if (lane == 0) { sh[w] = s; sh[4 + w] = s2; }
    __syncthreads();
    float S = sh[0] + sh[1] + sh[2] + sh[3];
    float S2 = sh[4] + sh[5] + sh[6] + sh[7];
    float mu = S * (1.f / Dv);
    float var = S2 * (1.f / Dv) - mu * mu;
    float rs = rsqrtf(var + 1e-5f);
#pragma unroll
    for (int i = 0; i < 4; i++) {
        int j = tid + i * 128;
        x[(size_t)n * Dv + j] += (v[i] - mu) * rs * g[j] + bl[j];
    }
}

// -------------------- host driver --------------------
extern "C" void kernel_launch(void* const* d_in, const int* in_sizes, int n_in,
                              void* d_out, int out_size) {
    const int*   tokens = (const int*)d_in[0];
    const float* emb    = (const float*)d_in[1];
    const float* Wq     = (const float*)d_in[2];
    const float* bq     = (const float*)d_in[3];
    const float* Wk     = (const float*)d_in[4];
    const float* bk     = (const float*)d_in[5];
    const float* Wv     = (const float*)d_in[6];
    const float* bv     = (const float*)d_in[7];
    const float* rfs    = (const float*)d_in[8];
    const float* ln1g   = (const float*)d_in[9];
    const float* ln1b   = (const float*)d_in[10];
    const float* ln2g   = (const float*)d_in[11];
    const float* ln2b   = (const float*)d_in[12];
    const float* WU     = (const float*)d_in[13];
    const float* bU     = (const float*)d_in[14];
    const float* WV     = (const float*)d_in[15];
    const float* bV     = (const float*)d_in[16];
    const float* Wout   = (const float*)d_in[17];
    const float* bout   = (const float*)d_in[18];
    float* out = (float*)d_out;

    static float *px = nullptr, *pa, *pq, *pk, *pv, *ph;
    if (!px) {
        cudaGetSymbolAddress((void**)&px, g_x);
        cudaGetSymbolAddress((void**)&pa, g_a);
        cudaGetSymbolAddress((void**)&pq, g_q);
        cudaGetSymbolAddress((void**)&pk, g_k);
        cudaGetSymbolAddress((void**)&pv, g_v);
        cudaGetSymbolAddress((void**)&ph, g_h);
    }

    embed_kernel<<<(NTOK * Dv + 255) / 256, 256>>>(tokens, emb);

    for (int l = 0; l < Lv; l++) {
        dim3 gQKV(Dv / 128, NTOK / 128);
        gemm_bias<<<gQKV, 256>>>(px, Wq + (size_t)l * Dv * Dv, bq + l * Dv, pq,
                                 NTOK, Dv, Dv, 0);
        gemm_bias<<<gQKV, 256>>>(px, Wk + (size_t)l * Dv * Dv, bk + l * Dv, pk,
                                 NTOK, Dv, Dv, 0);
        gemm_bias<<<gQKV, 256>>>(px, Wv + (size_t)l * Dv * Dv, bv + l * Dv, pv,
                                 NTOK, Dv, Dv, 0);

        favor_feat<<<NTOK * Hv, 64>>>(rfs + (size_t)l * Hv * HDv * HDv);
        attn_chunk<<<dim3(NCHUNK, Bv * Hv), 64>>>();
        attn_scan<<<Bv * Hv, 64>>>();
        attn_apply<<<dim3(NCHUNK, Bv * Hv), 64>>>();

        ln_add<<<NTOK, 128>>>(pa, ln1g + l * Dv, ln1b + l * Dv, px);

        gemm_bias<<<dim3(FFNv / 128, NTOK / 128), 256>>>(
            px, WU + (size_t)l * Dv * FFNv, bU + l * FFNv, ph, NTOK, FFNv, Dv, 1);
        gemm_bias<<<dim3(Dv / 128, NTOK / 128), 256>>>(
            ph, WV + (size_t)l * FFNv * Dv, bV + l * Dv, pa, NTOK, Dv, FFNv, 0);

        ln_add<<<NTOK, 128>>>(pa, ln2g + l * Dv, ln2b + l * Dv, px);
    }

    gemm_bias<<<dim3(VOCABv / 128, NTOK / 128), 256>>>(
        px, Wout, bout, out, NTOK, VOCABv, Dv, 0);
}

// round 2
// speedup vs baseline: 2.1417x; 2.1417x over previous
#include <cuda_runtime.h>
#include <cuda_bf16.h>
#include <math.h>
#include <stdint.h>

// Problem constants
#define Bv      2
#define Tv      2048
#define NTOK    (Bv * Tv)      // 4096
#define Dv      512
#define Hv      8
#define HDv     64
#define FFNv    2048
#define VOCABv  256
#define Lv      2
#define CHUNK   128
#define NCHUNK  (Tv / CHUNK)   // 16

// -------------------- scratch (device globals; no allocs) --------------------
__device__ float g_x[NTOK * Dv];
__device__ float g_a[NTOK * Dv];
__device__ float g_q[NTOK * Dv];
__device__ float g_k[NTOK * Dv];
__device__ float g_v[NTOK * Dv];
__device__ float g_qf[NTOK * Dv];
__device__ float g_kf[NTOK * Dv];
__device__ float g_h[NTOK * FFNv];
__device__ float g_S[Bv * Hv * NCHUNK * HDv * HDv];
__device__ float g_z[Bv * Hv * NCHUNK * HDv];

// -------------------- embedding + sinusoidal positions --------------------
__global__ void embed_kernel(const int* __restrict__ tokens,
                             const float* __restrict__ emb) {
    int idx = blockIdx.x * blockDim.x + threadIdx.x;
    if (idx >= NTOK * Dv) return;
    int n = idx >> 9;
    int j = idx & 511;
    int t = n & (Tv - 1);
    float val;
    const float c = 9.210340371976184f / 256.f;
    if (j < 256) {
        int tok = tokens[n];
        val = emb[tok * 256 + j];
    } else if (j < 384) {
        int i = j - 256;
        val = sinf((float)t * expf(-(2.f * (float)i) * c));
    } else {
        int i = j - 384;
        val = cosf((float)t * expf(-(2.f * (float)i) * c));
    }
    g_x[idx] = val;
}

// -------------------- tensor-core GEMM (bf16 hi/lo split, fp32-equivalent) ----
// C[M,N] = A[M,K] @ B[K,N] + bias (+gelu). BM=BN=128, BK=16, 256 threads.
// A*B ~= Ah*Bh + Al*Bh + Ah*Bl  (error ~2^-18, negligible)

#define PADA 24    // As row stride (bf16): conflict-free ldmatrix
#define PADB 136   // Bs row stride (bf16)

__device__ __forceinline__ void ldsm_x4(uint32_t* r, const void* p) {
    uint32_t a = (uint32_t)__cvta_generic_to_shared(p);
    asm volatile("ldmatrix.sync.aligned.m8n8.x4.shared.b16 {%0,%1,%2,%3},[%4];"
        : "=r"(r[0]), "=r"(r[1]), "=r"(r[2]), "=r"(r[3]) : "r"(a));
}
__device__ __forceinline__ void ldsm_x4_t(uint32_t* r, const void* p) {
    uint32_t a = (uint32_t)__cvta_generic_to_shared(p);
    asm volatile("ldmatrix.sync.aligned.m8n8.x4.trans.shared.b16 {%0,%1,%2,%3},[%4];"
        : "=r"(r[0]), "=r"(r[1]), "=r"(r[2]), "=r"(r[3]) : "r"(a));
}
__device__ __forceinline__ void mma16816(float* c, const uint32_t* a, const uint32_t* b) {
    asm volatile("mma.sync.aligned.m16n8k16.row.col.f32.bf16.bf16.f32 "
        "{%0,%1,%2,%3},{%4,%5,%6,%7},{%8,%9},{%0,%1,%2,%3};"
        : "+f"(c[0]), "+f"(c[1]), "+f"(c[2]), "+f"(c[3])
        : "r"(a[0]), "r"(a[1]), "r"(a[2]), "r"(a[3]), "r"(b[0]), "r"(b[1]));
}

__global__ void __launch_bounds__(256, 1)
gemm_tc(const float* __restrict__ A, const float* __restrict__ B,
        const float* __restrict__ bias, float* __restrict__ C,
        int M, int N, int K, int act) {
    __shared__ __nv_bfloat16 As[2][128][PADA];   // [hi/lo][m][k]
    __shared__ __nv_bfloat16 Bs[2][16][PADB];    // [hi/lo][k][n]

    int tid = threadIdx.x;
    int wid = tid >> 5, lane = tid & 31;
    int m_w = (wid >> 1) * 32, n_w = (wid & 1) * 64;
    int row0 = blockIdx.y * 128, col0 = blockIdx.x * 128;

    float acc[2][8][4];
#pragma unroll
    for (int i = 0; i < 2; i++)
#pragma unroll
        for (int j = 0; j < 8; j++)
#pragma unroll
            for (int q = 0; q < 4; q++) acc[i][j][q] = 0.f;

    float4 aR[2], bR[2];

    auto loadG = [&](int k0) {
#pragma unroll
        for (int s = 0; s < 2; s++) {
            int slot = tid + s * 256;
            int ar = slot >> 2, ac = (slot & 3) * 4;
            aR[s] = *(const float4*)(A + (size_t)(row0 + ar) * K + k0 + ac);
            int br = slot >> 5, bc = (slot & 31) * 4;
            bR[s] = *(const float4*)(B + (size_t)(k0 + br) * N + col0 + bc);
        }
    };
    auto storeS = [&]() {
#pragma unroll
        for (int s = 0; s < 2; s++) {
            int slot = tid + s * 256;
            int ar = slot >> 2, ac = (slot & 3) * 4;
            float av[4] = {aR[s].x, aR[s].y, aR[s].z, aR[s].w};
#pragma unroll
            for (int j = 0; j < 4; j += 2) {
                __nv_bfloat16 h0 = __float2bfloat16(av[j]);
                __nv_bfloat16 h1 = __float2bfloat16(av[j + 1]);
                __nv_bfloat16 l0 = __float2bfloat16(av[j] - __bfloat162float(h0));
                __nv_bfloat16 l1 = __float2bfloat16(av[j + 1] - __bfloat162float(h1));
                *(__nv_bfloat162*)&As[0][ar][ac + j] = __nv_bfloat162(h0, h1);
                *(__nv_bfloat162*)&As[1][ar][ac + j] = __nv_bfloat162(l0, l1);
            }
            int br = slot >> 5, bc = (slot & 31) * 4;
            float bvv[4] = {bR[s].x, bR[s].y, bR[s].z, bR[s].w};
#pragma unroll
            for (int j = 0; j < 4; j += 2) {
                __nv_bfloat16 h0 = __float2bfloat16(bvv[j]);
                __nv_bfloat16 h1 = __float2bfloat16(bvv[j + 1]);
                __nv_bfloat16 l0 = __float2bfloat16(bvv[j] - __bfloat162float(h0));
                __nv_bfloat16 l1 = __float2bfloat16(bvv[j + 1] - __bfloat162float(h1));
                *(__nv_bfloat162*)&Bs[0][br][bc + j] = __nv_bfloat162(h0, h1);
                *(__nv_bfloat162*)&Bs[1][br][bc + j] = __nv_bfloat162(l0, l1);
            }
        }
    };
    auto compute = [&]() {
        uint32_t Ah[2][4], Al[2][4], Bh[8][2], Bl[8][2];
#pragma unroll
        for (int i = 0; i < 2; i++) {
            ldsm_x4(Ah[i], &As[0][m_w + i * 16 + (lane & 15)][(lane >> 4) * 8]);
            ldsm_x4(Al[i], &As[1][m_w + i * 16 + (lane & 15)][(lane >> 4) * 8]);
        }
#pragma unroll
        for (int p = 0; p < 4; p++) {
            uint32_t r[4];
            ldsm_x4_t(r, &Bs[0][lane & 15][n_w + p * 16 + (lane >> 4) * 8]);
            Bh[2 * p][0] = r[0]; Bh[2 * p][1] = r[1];
            Bh[2 * p + 1][0] = r[2]; Bh[2 * p + 1][1] = r[3];
            ldsm_x4_t(r, &Bs[1][lane & 15][n_w + p * 16 + (lane >> 4) * 8]);
            Bl[2 * p][0] = r[0]; Bl[2 * p][1] = r[1];
            Bl[2 * p + 1][0] = r[2]; Bl[2 * p + 1][1] = r[3];
        }
#pragma unroll
        for (int i = 0; i < 2; i++)
#pragma unroll
            for (int j = 0; j < 8; j++) {
                mma16816(acc[i][j], Ah[i], Bh[j]);
                mma16816(acc[i][j], Al[i], Bh[j]);
                mma16816(acc[i][j], Ah[i], Bl[j]);
            }
    };

    loadG(0);
    storeS();
    __syncthreads();
    for (int k0 = 16; k0 < K; k0 += 16) {
        loadG(k0);
        compute();
        __syncthreads();
        storeS();
        __syncthreads();
    }
    compute();

    // epilogue: bias (+gelu), fp32 out
    int g = lane >> 2, tg = lane & 3;
#pragma unroll
    for (int i = 0; i < 2; i++) {
#pragma unroll
        for (int j = 0; j < 8; j++) {
            int cc = col0 + n_w + j * 8 + tg * 2;
            float b0 = bias[cc], b1 = bias[cc + 1];
#pragma unroll
            for (int half = 0; half < 2; half++) {
                int r = row0 + m_w + i * 16 + g + half * 8;
                float v0 = acc[i][j][half * 2 + 0] + b0;
                float v1 = acc[i][j][half * 2 + 1] + b1;
                if (act == 1) {
                    v0 = 0.5f * v0 * (1.f + erff(v0 * 0.7071067811865475f));
                    v1 = 0.5f * v1 * (1.f + erff(v1 * 0.7071067811865475f));
                }
                *(float2*)(C + (size_t)r * N + cc) = make_float2(v0, v1);
            }
        }
    }
}

// -------------------- FAVOR+ feature map --------------------
__global__ void __launch_bounds__(64)
favor_feat(const float* __restrict__ rfs) {
    int gid = blockIdx.x;
    int h = gid % Hv;
    int n = gid / Hv;
    int tid = threadIdx.x;
    int lane = tid & 31, w = tid >> 5;
    __shared__ float sxq[64], sxk[64], sred[4];
    const float sc = 0.3535533905932738f;
    int base = n * Dv + h * HDv;
    float qv = g_q[base + tid] * sc;
    float kv = g_k[base + tid] * sc;
    sxq[tid] = qv;
    sxk[tid] = kv;
    float pq = qv * qv, pk = kv * kv;
#pragma unroll
    for (int off = 16; off; off >>= 1) {
        pq += __shfl_down_sync(0xffffffffu, pq, off);
        pk += __shfl_down_sync(0xffffffffu, pk, off);
    }
    if (lane == 0) { sred[w] = pq; sred[2 + w] = pk; }
    __syncthreads();
    float sq2 = sred[0] + sred[1];
    float sk2 = sred[2] + sred[3];
    const float* rf = rfs + h * HDv * HDv + tid;
    float dq = 0.f, dk = 0.f;
#pragma unroll 8
    for (int d = 0; d < HDv; d++) {
        float r = rf[d * HDv];
        dq += sxq[d] * r;
        dk += sxk[d] * r;
    }
    g_qf[base + tid] = expf(dq - 0.5f * sq2);
    g_kf[base + tid] = expf(dk - 0.5f * sk2);
}

// -------------------- phase 1: per-chunk sums --------------------
__global__ void __launch_bounds__(64)
attn_chunk() {
    int c = blockIdx.x, bh = blockIdx.y;
    int b = bh / Hv, h = bh % Hv;
    int d = threadIdx.x;
    float S[64];
#pragma unroll
    for (int m = 0; m < 64; m++) S[m] = 0.f;
    float z = 0.f;
    __shared__ float sk[64];
    for (int t = c * CHUNK; t < (c + 1) * CHUNK; t++) {
        int base = (b * Tv + t) * Dv + h * HDv;
        sk[d] = g_kf[base + d];
        __syncthreads();
        float vd = g_v[base + d];
        z += sk[d];
#pragma unroll
        for (int m = 0; m < 64; m++) S[m] += sk[m] * vd;
        __syncthreads();
    }
    int sb = (bh * NCHUNK + c) * 4096;
#pragma unroll
    for (int m = 0; m < 64; m++) g_S[sb + m * 64 + d] = S[m];
    g_z[(bh * NCHUNK + c) * 64 + d] = z;
}

// -------------------- phase 2: exclusive scan over chunks --------------------
__global__ void __launch_bounds__(64)
attn_scan() {
    int bh = blockIdx.x, d = threadIdx.x;
    for (int m = 0; m < 64; m++) {
        float acc = 0.f;
        for (int c = 0; c < NCHUNK; c++) {
            int idx = (bh * NCHUNK + c) * 4096 + m * 64 + d;
            float t = g_S[idx];
            g_S[idx] = acc;
            acc += t;
        }
    }
    float za = 0.f;
    for (int c = 0; c < NCHUNK; c++) {
        int idx = (bh * NCHUNK + c) * 64 + d;
        float t = g_z[idx];
        g_z[idx] = za;
        za += t;
    }
}

// -------------------- phase 3: replay + output --------------------
__global__ void __launch_bounds__(64)
attn_apply() {
    int c = blockIdx.x, bh = blockIdx.y;
    int b = bh / Hv, h = bh % Hv;
    int d = threadIdx.x;
    int lane = d & 31, w = d >> 5;
    float S[64];
    int sb = (bh * NCHUNK + c) * 4096;
#pragma unroll
    for (int m = 0; m < 64; m++) S[m] = g_S[sb + m * 64 + d];
    float z = g_z[(bh * NCHUNK + c) * 64 + d];
    __shared__ float sk[64], sq[64], sred[2];
    for (int t = c * CHUNK; t < (c + 1) * CHUNK; t++) {
        int base = (b * Tv + t) * Dv + h * HDv;
        sk[d] = g_kf[base + d];
        sq[d] = g_qf[base + d];
        __syncthreads();
        z += sk[d];
        float p = sq[d] * z;
#pragma unroll
        for (int off = 16; off; off >>= 1) p += __shfl_down_sync(0xffffffffu, p, off);
        if (lane == 0) sred[w] = p;
        float vd = g_v[base + d];
        float num = 0.f;
#pragma unroll
        for (int m = 0; m < 64; m++) {
            S[m] += sk[m] * vd;
            num += sq[m] * S[m];
        }
        __syncthreads();
        float den = sred[0] + sred[1];
        g_a[base + d] = num / (den + 1e-16f);
    }
}

// -------------------- LayerNorm + residual add --------------------
__global__ void __launch_bounds__(128)
ln_add(const float* __restrict__ a, const float* __restrict__ g,
       const float* __restrict__ bl, float* __restrict__ x) {
    int n = blockIdx.x, tid = threadIdx.x;
    int lane = tid & 31, w = tid >> 5;
    const float* ar = a + (size_t)n * Dv;
    float v[4];
    float s = 0.f, s2 = 0.f;
#pragma unroll
    for (int i = 0; i < 4; i++) {
        float t = ar[tid + i * 128];
        v[i] = t;
        s += t;
        s2 += t * t;
    }
    __shared__ float sh[8];
#pragma unroll
    for (int off = 16; off; off >>= 1) {
        s += __shfl_down_sync(0xffffffffu, s, off);
        s2 += __shfl_down_sync(0xffffffffu, s2, off);
    }
    if (lane == 0) { sh[w] = s; sh[4 + w] = s2; }
    __syncthreads();
    float S = sh[0] + sh[1] + sh[2] + sh[3];
    float S2 = sh[4] + sh[5] + sh[6] + sh[7];
    float mu = S * (1.f / Dv);
    float var = S2 * (1.f / Dv) - mu * mu;
    float rs = rsqrtf(var + 1e-5f);
#pragma unroll
    for (int i = 0; i < 4; i++) {
        int j = tid + i * 128;
        x[(size_t)n * Dv + j] += (v[i] - mu) * rs * g[j] + bl[j];
    }
}

// -------------------- host driver --------------------
extern "C" void kernel_launch(void* const* d_in, const int* in_sizes, int n_in,
                              void* d_out, int out_size) {
    const int*   tokens = (const int*)d_in[0];
    const float* emb    = (const float*)d_in[1];
    const float* Wq     = (const float*)d_in[2];
    const float* bq     = (const float*)d_in[3];
    const float* Wk     = (const float*)d_in[4];
    const float* bk     = (const float*)d_in[5];
    const float* Wv     = (const float*)d_in[6];
    const float* bv     = (const float*)d_in[7];
    const float* rfs    = (const float*)d_in[8];
    const float* ln1g   = (const float*)d_in[9];
    const float* ln1b   = (const float*)d_in[10];
    const float* ln2g   = (const float*)d_in[11];
    const float* ln2b   = (const float*)d_in[12];
    const float* WU     = (const float*)d_in[13];
    const float* bU     = (const float*)d_in[14];
    const float* WV     = (const float*)d_in[15];
    const float* bV     = (const float*)d_in[16];
    const float* Wout   = (const float*)d_in[17];
    const float* bout   = (const float*)d_in[18];
    float* out = (float*)d_out;

    static float *px = nullptr, *pa, *pq, *pk, *pv, *ph;
    if (!px) {
        cudaGetSymbolAddress((void**)&px, g_x);
        cudaGetSymbolAddress((void**)&pa, g_a);
        cudaGetSymbolAddress((void**)&pq, g_q);
        cudaGetSymbolAddress((void**)&pk, g_k);
        cudaGetSymbolAddress((void**)&pv, g_v);
        cudaGetSymbolAddress((void**)&ph, g_h);
    }

    embed_kernel<<<(NTOK * Dv + 255) / 256, 256>>>(tokens, emb);

    for (int l = 0; l < Lv; l++) {
        dim3 gQKV(Dv / 128, NTOK / 128);
        gemm_tc<<<gQKV, 256>>>(px, Wq + (size_t)l * Dv * Dv, bq + l * Dv, pq,
                               NTOK, Dv, Dv, 0);
        gemm_tc<<<gQKV, 256>>>(px, Wk + (size_t)l * Dv * Dv, bk + l * Dv, pk,
                               NTOK, Dv, Dv, 0);
        gemm_tc<<<gQKV, 256>>>(px, Wv + (size_t)l * Dv * Dv, bv + l * Dv, pv,
                               NTOK, Dv, Dv, 0);

        favor_feat<<<NTOK * Hv, 64>>>(rfs + (size_t)l * Hv * HDv * HDv);
        attn_chunk<<<dim3(NCHUNK, Bv * Hv), 64>>>();
        attn_scan<<<Bv * Hv, 64>>>();
        attn_apply<<<dim3(NCHUNK, Bv * Hv), 64>>>();

        ln_add<<<NTOK, 128>>>(pa, ln1g + l * Dv, ln1b + l * Dv, px);

        gemm_tc<<<dim3(FFNv / 128, NTOK / 128), 256>>>(
            px, WU + (size_t)l * Dv * FFNv, bU + l * FFNv, ph, NTOK, FFNv, Dv, 1);
        gemm_tc<<<dim3(Dv / 128, NTOK / 128), 256>>>(
            ph, WV + (size_t)l * FFNv * Dv, bV + l * Dv, pa, NTOK, Dv, FFNv, 0);

        ln_add<<<NTOK, 128>>>(pa, ln2g + l * Dv, ln2b + l * Dv, px);
    }

    gemm_tc<<<dim3(VOCABv / 128, NTOK / 128), 256>>>(
        px, Wout, bout, out, NTOK, VOCABv, Dv, 0);
}

// round 3
// speedup vs baseline: 2.5174x; 1.1754x over previous
#include <cuda_runtime.h>
#include <cuda_bf16.h>
#include <math.h>
#include <stdint.h>

// Problem constants
#define Bv      2
#define Tv      2048
#define NTOK    (Bv * Tv)      // 4096
#define Dv      512
#define Hv      8
#define HDv     64
#define FFNv    2048
#define VOCABv  256
#define Lv      2
#define CHUNK   64
#define NCHUNK  (Tv / CHUNK)   // 32

// weight region offsets (elements) in the hi/lo weight pools
#define OFF_WQ  0
#define OFF_WK  (OFF_WQ + Lv * Dv * Dv)
#define OFF_WV  (OFF_WK + Lv * Dv * Dv)
#define OFF_WU  (OFF_WV + Lv * Dv * Dv)
#define OFF_WD  (OFF_WU + Lv * Dv * FFNv)
#define OFF_WO  (OFF_WD + Lv * FFNv * Dv)
#define W_TOTAL (OFF_WO + Dv * VOCABv)

// -------------------- scratch (device globals; no allocs) --------------------
__device__ float g_x[NTOK * Dv];
__device__ float g_a[NTOK * Dv];
__device__ float g_q[NTOK * Dv];
__device__ float g_k[NTOK * Dv];
__device__ float g_v[NTOK * Dv];
__device__ float g_qf[NTOK * Dv];
__device__ float g_kf[NTOK * Dv];
__device__ float g_S[Bv * Hv * NCHUNK * HDv * HDv];
__device__ float g_z[Bv * Hv * NCHUNK * HDv];
__device__ __nv_bfloat16 g_xh[NTOK * Dv];
__device__ __nv_bfloat16 g_xl[NTOK * Dv];
__device__ __nv_bfloat16 g_hh[NTOK * FFNv];
__device__ __nv_bfloat16 g_hl[NTOK * FFNv];
__device__ __nv_bfloat16 g_wh[W_TOTAL];
__device__ __nv_bfloat16 g_wl[W_TOTAL];

__device__ __forceinline__ void split_bf16(float v, __nv_bfloat16& h, __nv_bfloat16& l) {
    h = __float2bfloat16(v);
    l = __float2bfloat16(v - __bfloat162float(h));
}

// -------------------- weight fp32 -> bf16 hi/lo --------------------
__global__ void convw(const float* __restrict__ src, __nv_bfloat16* __restrict__ dh,
                      __nv_bfloat16* __restrict__ dl, int n) {
    int i = blockIdx.x * blockDim.x + threadIdx.x;
    if (i >= n) return;
    __nv_bfloat16 h, l;
    split_bf16(src[i], h, l);
    dh[i] = h;
    dl[i] = l;
}

// -------------------- embedding + sinusoidal positions --------------------
__global__ void embed_kernel(const int* __restrict__ tokens,
                             const float* __restrict__ emb) {
    int idx = blockIdx.x * blockDim.x + threadIdx.x;
    if (idx >= NTOK * Dv) return;
    int n = idx >> 9;
    int j = idx & 511;
    int t = n & (Tv - 1);
    float val;
    const float c = 9.210340371976184f / 256.f;
    if (j < 256) {
        int tok = tokens[n];
        val = emb[tok * 256 + j];
    } else if (j < 384) {
        int i = j - 256;
        val = sinf((float)t * expf(-(2.f * (float)i) * c));
    } else {
        int i = j - 384;
        val = cosf((float)t * expf(-(2.f * (float)i) * c));
    }
    g_x[idx] = val;
    __nv_bfloat16 h, l;
    split_bf16(val, h, l);
    g_xh[idx] = h;
    g_xl[idx] = l;
}

// -------------------- tensor-core GEMM, cp.async double-buffered --------------------
// C = A@B + bias; A,B given as bf16 hi/lo pairs (A*B ~= AhBh + AlBh + AhBl).
// BM=BN=128, BK=32, 256 threads (8 warps, 32x64 warp tiles).
// mode 0: fp32 out. mode 1: gelu, write bf16 hi/lo (Ch/Cl).

__device__ __forceinline__ void ldsm_x4(uint32_t* r, const void* p) {
    uint32_t a = (uint32_t)__cvta_generic_to_shared(p);
    asm volatile("ldmatrix.sync.aligned.m8n8.x4.shared.b16 {%0,%1,%2,%3},[%4];"
        : "=r"(r[0]), "=r"(r[1]), "=r"(r[2]), "=r"(r[3]) : "r"(a));
}
__device__ __forceinline__ void ldsm_x4_t(uint32_t* r, const void* p) {
    uint32_t a = (uint32_t)__cvta_generic_to_shared(p);
    asm volatile("ldmatrix.sync.aligned.m8n8.x4.trans.shared.b16 {%0,%1,%2,%3},[%4];"
        : "=r"(r[0]), "=r"(r[1]), "=r"(r[2]), "=r"(r[3]) : "r"(a));
}
__device__ __forceinline__ void mma16816(float* c, const uint32_t* a, const uint32_t* b) {
    asm volatile("mma.sync.aligned.m16n8k16.row.col.f32.bf16.bf16.f32 "
        "{%0,%1,%2,%3},{%4,%5,%6,%7},{%8,%9},{%0,%1,%2,%3};"
        : "+f"(c[0]), "+f"(c[1]), "+f"(c[2]), "+f"(c[3])
        : "r"(a[0]), "r"(a[1]), "r"(a[2]), "r"(a[3]), "r"(b[0]), "r"(b[1]));
}
__device__ __forceinline__ void cp16(void* smem, const void* gmem) {
    uint32_t s = (uint32_t)__cvta_generic_to_shared(smem);
    asm volatile("cp.async.cg.shared.global [%0], [%1], 16;" :: "r"(s), "l"(gmem));
}
#define CP_COMMIT() asm volatile("cp.async.commit_group;")
#define CP_WAIT(n)  asm volatile("cp.async.wait_group %0;" :: "n"(n))

#define PADA 40    // As row stride (bf16)
#define PADB 136   // Bs row stride (bf16)
#define SM_ASH 0
#define SM_ASL 20480
#define SM_BSH 40960
#define SM_BSL 58368
#define SM_TOTAL 75776

__global__ void __launch_bounds__(256, 1)
gemm_tc(const __nv_bfloat16* __restrict__ Ahg, const __nv_bfloat16* __restrict__ Alg,
        const __nv_bfloat16* __restrict__ Bhg, const __nv_bfloat16* __restrict__ Blg,
        const float* __restrict__ bias, float* __restrict__ C,
        __nv_bfloat16* __restrict__ Ch, __nv_bfloat16* __restrict__ Cl,
        int M, int N, int K, int mode) {
    extern __shared__ char smraw[];
    __nv_bfloat16* AsH = (__nv_bfloat16*)(smraw + SM_ASH);
    __nv_bfloat16* AsL = (__nv_bfloat16*)(smraw + SM_ASL);
    __nv_bfloat16* BsH = (__nv_bfloat16*)(smraw + SM_BSH);
    __nv_bfloat16* BsL = (__nv_bfloat16*)(smraw + SM_BSL);

    int tid = threadIdx.x;
    int wid = tid >> 5, lane = tid & 31;
    int m_w = (wid >> 1) * 32, n_w = (wid & 1) * 64;
    int row0 = blockIdx.y * 128, col0 = blockIdx.x * 128;

    float acc[2][8][4];
#pragma unroll
    for (int i = 0; i < 2; i++)
#pragma unroll
        for (int j = 0; j < 8; j++)
#pragma unroll
            for (int q = 0; q < 4; q++) acc[i][j][q] = 0.f;

    // per-thread load coords
    int ar = tid >> 2, ac = (tid & 3) * 8;           // A: 128 rows x 4 chunks
    int br = tid >> 4, bc = (tid & 15) * 8;          // B: 16(x2) rows x 16 chunks

    auto loadStage = [&](int st, int k0) {
#pragma unroll
        for (int s = 0; s < 2; s++) {
            int arr = ar, acc_ = ac;                 // A chunk id = tid + s*256
            // chunk c = tid + s*256 -> row = c>>2 (s adds 64 rows), col same
            int a_row = arr + s * 64;
            size_t ga = (size_t)(row0 + a_row) * K + k0 + acc_;
            int sa = (st * 128 + a_row) * PADA + acc_;
            cp16(AsH + sa, Ahg + ga);
            cp16(AsL + sa, Alg + ga);
            int b_row = br + s * 16;
            size_t gb = (size_t)(k0 + b_row) * N + col0 + bc;
            int sb = (st * 32 + b_row) * PADB + bc;
            cp16(BsH + sb, Bhg + gb);
            cp16(BsL + sb, Blg + gb);
        }
        CP_COMMIT();
    };

    auto compute = [&](int st) {
#pragma unroll
        for (int kk = 0; kk < 32; kk += 16) {
            uint32_t Ahf[2][4], Alf[2][4], Bhf[8][2], Blf[8][2];
#pragma unroll
            for (int i = 0; i < 2; i++) {
                int idx = (st * 128 + m_w + i * 16 + (lane & 15)) * PADA + kk + (lane >> 4) * 8;
                ldsm_x4(Ahf[i], AsH + idx);
                ldsm_x4(Alf[i], AsL + idx);
            }
#pragma unroll
            for (int p = 0; p < 4; p++) {
                int idx = (st * 32 + kk + (lane & 15)) * PADB + n_w + p * 16 + (lane >> 4) * 8;
                uint32_t r[4];
                ldsm_x4_t(r, BsH + idx);
                Bhf[2 * p][0] = r[0]; Bhf[2 * p][1] = r[1];
                Bhf[2 * p + 1][0] = r[2]; Bhf[2 * p + 1][1] = r[3];
                ldsm_x4_t(r, BsL + idx);
                Blf[2 * p][0] = r[0]; Blf[2 * p][1] = r[1];
                Blf[2 * p + 1][0] = r[2]; Blf[2 * p + 1][1] = r[3];
            }
#pragma unroll
            for (int i = 0; i < 2; i++)
#pragma unroll
                for (int j = 0; j < 8; j++) {
                    mma16816(acc[i][j], Ahf[i], Bhf[j]);
                    mma16816(acc[i][j], Alf[i], Bhf[j]);
                    mma16816(acc[i][j], Ahf[i], Blf[j]);
                }
        }
    };

    int nsteps = K / 32;
    loadStage(0, 0);
    for (int s = 0; s < nsteps; s++) {
        if (s + 1 < nsteps) {
            loadStage((s + 1) & 1, (s + 1) * 32);
            CP_WAIT(1);
        } else {
            CP_WAIT(0);
        }
        __syncthreads();
        compute(s & 1);
        __syncthreads();
    }

    // epilogue
    int g = lane >> 2, tg = lane & 3;
#pragma unroll
    for (int i = 0; i < 2; i++) {
#pragma unroll
        for (int j = 0; j < 8; j++) {
            int cc = col0 + n_w + j * 8 + tg * 2;
            float b0 = bias[cc], b1 = bias[cc + 1];
#pragma unroll
            for (int half = 0; half < 2; half++) {
                int r = row0 + m_w + i * 16 + g + half * 8;
                float v0 = acc[i][j][half * 2 + 0] + b0;
                float v1 = acc[i][j][half * 2 + 1] + b1;
                if (mode == 1) {
                    v0 = 0.5f * v0 * (1.f + erff(v0 * 0.7071067811865475f));
                    v1 = 0.5f * v1 * (1.f + erff(v1 * 0.7071067811865475f));
                    __nv_bfloat16 h0, l0, h1, l1;
                    split_bf16(v0, h0, l0);
                    split_bf16(v1, h1, l1);
                    *(__nv_bfloat162*)(Ch + (size_t)r * N + cc) = __nv_bfloat162(h0, h1);
                    *(__nv_bfloat162*)(Cl + (size_t)r * N + cc) = __nv_bfloat162(l0, l1);
                } else {
                    *(float2*)(C + (size_t)r * N + cc) = make_float2(v0, v1);
                }
            }
        }
    }
}

// -------------------- FAVOR+ feature map (smem-tiled) --------------------
// grid (NTOK/32, Hv), 128 threads. rf[h] staged once per 32 tokens.
__global__ void __launch_bounds__(128)
favor_feat(const float* __restrict__ rfs) {
    int tile = blockIdx.x, h = blockIdx.y;
    __shared__ float rf[64][64];
    __shared__ float sq[32][68], sk[32][68];
    int tid = threadIdx.x;
    const float* rfh = rfs + h * 4096;
    for (int i = tid; i < 4096; i += 128) rf[i >> 6][i & 63] = rfh[i];
    const float sc = 0.3535533905932738f;  // 64^{-1/4}
    for (int i = tid; i < 2048; i += 128) {
        int tl = i >> 6, d = i & 63;
        int gidx = (tile * 32 + tl) * Dv + h * HDv + d;
        sq[tl][d] = g_q[gidx] * sc;
        sk[tl][d] = g_k[gidx] * sc;
    }
    __syncthreads();
    int tl = tid >> 2, ms = (tid & 3) << 4;
    float s2q = 0.f, s2k = 0.f;
#pragma unroll 8
    for (int d = 0; d < 64; d++) {
        float a = sq[tl][d], b = sk[tl][d];
        s2q += a * a;
        s2k += b * b;
    }
    float dq[16], dk[16];
#pragma unroll
    for (int mi = 0; mi < 16; mi++) { dq[mi] = 0.f; dk[mi] = 0.f; }
#pragma unroll 4
    for (int d = 0; d < 64; d++) {
        float a = sq[tl][d], b = sk[tl][d];
#pragma unroll
        for (int m4 = 0; m4 < 4; m4++) {
            float4 rv = *(const float4*)&rf[d][ms + m4 * 4];
            float rr[4] = {rv.x, rv.y, rv.z, rv.w};
#pragma unroll
            for (int q = 0; q < 4; q++) {
                dq[m4 * 4 + q] += a * rr[q];
                dk[m4 * 4 + q] += b * rr[q];
            }
        }
    }
    int base = (tile * 32 + tl) * Dv + h * HDv + ms;
#pragma unroll
    for (int mi = 0; mi < 16; mi++) {
        g_qf[base + mi] = expf(dq[mi] - 0.5f * s2q);
        g_kf[base + mi] = expf(dk[mi] - 0.5f * s2k);
    }
}

// -------------------- phase 1: per-chunk sums --------------------
__global__ void __launch_bounds__(64)
attn_chunk() {
    int c = blockIdx.x, bh = blockIdx.y;
    int b = bh / Hv, h = bh % Hv;
    int d = threadIdx.x;
    float S[64];
#pragma unroll
    for (int m = 0; m < 64; m++) S[m] = 0.f;
    float z = 0.f;
    __shared__ float sk[64];
    for (int t = c * CHUNK; t < (c + 1) * CHUNK; t++) {
        int base = (b * Tv + t) * Dv + h * HDv;
        sk[d] = g_kf[base + d];
        __syncthreads();
        float vd = g_v[base + d];
        z += sk[d];
#pragma unroll
        for (int m = 0; m < 64; m++) S[m] += sk[m] * vd;
        __syncthreads();
    }
    int sb = (bh * NCHUNK + c) * 4096;
#pragma unroll
    for (int m = 0; m < 64; m++) g_S[sb + m * 64 + d] = S[m];
    g_z[(bh * NCHUNK + c) * 64 + d] = z;
}

// -------------------- phase 2: exclusive scans over chunks --------------------
__global__ void __launch_bounds__(64)
attn_scan_S() {
    int bh = blockIdx.x >> 6, m = blockIdx.x & 63, d = threadIdx.x;
    float v[NCHUNK];
#pragma unroll
    for (int c = 0; c < NCHUNK; c++)
        v[c] = g_S[((bh * NCHUNK + c) << 12) + m * 64 + d];
    float acc = 0.f;
#pragma unroll
    for (int c = 0; c < NCHUNK; c++) {
        g_S[((bh * NCHUNK + c) << 12) + m * 64 + d] = acc;
        acc += v[c];
    }
}
__global__ void __launch_bounds__(64)
attn_scan_z() {
    int bh = blockIdx.x, d = threadIdx.x;
    float v[NCHUNK];
#pragma unroll
    for (int c = 0; c < NCHUNK; c++) v[c] = g_z[(bh * NCHUNK + c) * 64 + d];
    float acc = 0.f;
#pragma unroll
    for (int c = 0; c < NCHUNK; c++) {
        g_z[(bh * NCHUNK + c) * 64 + d] = acc;
        acc += v[c];
    }
}

// -------------------- phase 3: replay + output --------------------
__global__ void __launch_bounds__(64)
attn_apply() {
    int c = blockIdx.x, bh = blockIdx.y;
    int b = bh / Hv, h = bh % Hv;
    int d = threadIdx.x;
    int lane = d & 31, w = d >> 5;
    float S[64];
    int sb = (bh * NCHUNK + c) * 4096;
#pragma unroll
    for (int m = 0; m < 64; m++) S[m] = g_S[sb + m * 64 + d];
    float z = g_z[(bh * NCHUNK + c) * 64 + d];
    __shared__ float sk[64], sq[64], sred[2];
    for (int t = c * CHUNK; t < (c + 1) * CHUNK; t++) {
        int base = (b * Tv + t) * Dv + h * HDv;
        sk[d] = g_kf[base + d];
        sq[d] = g_qf[base + d];
        __syncthreads();
        z += sk[d];
        float p = sq[d] * z;
#pragma unroll
        for (int off = 16; off; off >>= 1) p += __shfl_down_sync(0xffffffffu, p, off);
        if (lane == 0) sred[w] = p;
        float vd = g_v[base + d];
        float num = 0.f;
#pragma unroll
        for (int m = 0; m < 64; m++) {
            S[m] += sk[m] * vd;
            num += sq[m] * S[m];
        }
        __syncthreads();
        float den = sred[0] + sred[1];
        g_a[base + d] = num / (den + 1e-16f);
    }
}

// -------------------- LayerNorm + residual add (+ bf16 hi/lo of new x) ----------
__global__ void __launch_bounds__(128)
ln_add(const float* __restrict__ a, const float* __restrict__ g,
       const float* __restrict__ bl, float* __restrict__ x) {
    int n = blockIdx.x, tid = threadIdx.x;
    int lane = tid & 31, w = tid >> 5;
    const float* ar = a + (size_t)n * Dv;
    float v[4];
    float s = 0.f, s2 = 0.f;
#pragma unroll
    for (int i = 0; i < 4; i++) {
        float t = ar[tid + i * 128];
        v[i] = t;
        s += t;
        s2 += t * t;
    }
    __shared__ float sh[8];
#pragma unroll
    for (int off = 16; off; off >>= 1) {
        s += __shfl_down_sync(0xffffffffu, s, off);
        s2 += __shfl_down_sync(0xffffffffu, s2, off);
    }
    if (lane == 0) { sh[w] = s; sh[4 + w] = s2; }
    __syncthreads();
    float S = sh[0] + sh[1] + sh[2] + sh[3];
    float S2 = sh[4] + sh[5] + sh[6] + sh[7];
    float mu = S * (1.f / Dv);
    float var = S2 * (1.f / Dv) - mu * mu;
    float rs = rsqrtf(var + 1e-5f);
#pragma unroll
    for (int i = 0; i < 4; i++) {
        int j = tid + i * 128;
        size_t idx = (size_t)n * Dv + j;
        float nv = x[idx] + (v[i] - mu) * rs * g[j] + bl[j];
        x[idx] = nv;
        __nv_bfloat16 h, l;
        split_bf16(nv, h, l);
        g_xh[idx] = h;
        g_xl[idx] = l;
    }
}

// -------------------- host driver --------------------
extern "C" void kernel_launch(void* const* d_in, const int* in_sizes, int n_in,
                              void* d_out, int out_size) {
    const int*   tokens = (const int*)d_in[0];
    const float* emb    = (const float*)d_in[1];
    const float* Wq     = (const float*)d_in[2];
    const float* bq     = (const float*)d_in[3];
    const float* Wk     = (const float*)d_in[4];
    const float* bk     = (const float*)d_in[5];
    const float* Wv     = (const float*)d_in[6];
    const float* bv     = (const float*)d_in[7];
    const float* rfs    = (const float*)d_in[8];
    const float* ln1g   = (const float*)d_in[9];
    const float* ln1b   = (const float*)d_in[10];
    const float* ln2g   = (const float*)d_in[11];
    const float* ln2b   = (const float*)d_in[12];
    const float* WU     = (const float*)d_in[13];
    const float* bU     = (const float*)d_in[14];
    const float* WV     = (const float*)d_in[15];
    const float* bV     = (const float*)d_in[16];
    const float* Wout   = (const float*)d_in[17];
    const float* bout   = (const float*)d_in[18];
    float* out = (float*)d_out;

    static float *px = nullptr, *pa, *pq, *pk, *pv;
    static __nv_bfloat16 *pxh, *pxl, *phh, *phl, *pwh, *pwl;
    if (!px) {
        cudaGetSymbolAddress((void**)&px, g_x);
        cudaGetSymbolAddress((void**)&pa, g_a);
        cudaGetSymbolAddress((void**)&pq, g_q);
        cudaGetSymbolAddress((void**)&pk, g_k);
        cudaGetSymbolAddress((void**)&pv, g_v);
        cudaGetSymbolAddress((void**)&pxh, g_xh);
        cudaGetSymbolAddress((void**)&pxl, g_xl);
        cudaGetSymbolAddress((void**)&phh, g_hh);
        cudaGetSymbolAddress((void**)&phl, g_hl);
        cudaGetSymbolAddress((void**)&pwh, g_wh);
        cudaGetSymbolAddress((void**)&pwl, g_wl);
        cudaFuncSetAttribute(gemm_tc, cudaFuncAttributeMaxDynamicSharedMemorySize, SM_TOTAL);
    }

    // weights -> bf16 hi/lo
    auto cw = [&](const float* src, int off, int n) {
        convw<<<(n + 255) / 256, 256>>>(src, pwh + off, pwl + off, n);
    };
    cw(Wq, OFF_WQ, Lv * Dv * Dv);
    cw(Wk, OFF_WK, Lv * Dv * Dv);
    cw(Wv, OFF_WV, Lv * Dv * Dv);
    cw(WU, OFF_WU, Lv * Dv * FFNv);
    cw(WV, OFF_WD, Lv * FFNv * Dv);
    cw(Wout, OFF_WO, Dv * VOCABv);

    embed_kernel<<<(NTOK * Dv + 255) / 256, 256>>>(tokens, emb);

    for (int l = 0; l < Lv; l++) {
        dim3 gQKV(Dv / 128, NTOK / 128);
        gemm_tc<<<gQKV, 256, SM_TOTAL>>>(pxh, pxl, pwh + OFF_WQ + l * Dv * Dv,
                                         pwl + OFF_WQ + l * Dv * Dv, bq + l * Dv,
                                         pq, nullptr, nullptr, NTOK, Dv, Dv, 0);
        gemm_tc<<<gQKV, 256, SM_TOTAL>>>(pxh, pxl, pwh + OFF_WK + l * Dv * Dv,
                                         pwl + OFF_WK + l * Dv * Dv, bk + l * Dv,
                                         pk, nullptr, nullptr, NTOK, Dv, Dv, 0);
        gemm_tc<<<gQKV, 256, SM_TOTAL>>>(pxh, pxl, pwh + OFF_WV + l * Dv * Dv,
                                         pwl + OFF_WV + l * Dv * Dv, bv + l * Dv,
                                         pv, nullptr, nullptr, NTOK, Dv, Dv, 0);

        favor_feat<<<dim3(NTOK / 32, Hv), 128>>>(rfs + (size_t)l * Hv * HDv * HDv);
        attn_chunk<<<dim3(NCHUNK, Bv * Hv), 64>>>();
        attn_scan_S<<<Bv * Hv * HDv, 64>>>();
        attn_scan_z<<<Bv * Hv, 64>>>();
        attn_apply<<<dim3(NCHUNK, Bv * Hv), 64>>>();

        ln_add<<<NTOK, 128>>>(pa, ln1g + l * Dv, ln1b + l * Dv, px);

        gemm_tc<<<dim3(FFNv / 128, NTOK / 128), 256, SM_TOTAL>>>(
            pxh, pxl, pwh + OFF_WU + l * Dv * FFNv, pwl + OFF_WU + l * Dv * FFNv,
            bU + l * FFNv, nullptr, phh, phl, NTOK, FFNv, Dv, 1);
        gemm_tc<<<dim3(Dv / 128, NTOK / 128), 256, SM_TOTAL>>>(
            phh, phl, pwh + OFF_WD + l * FFNv * Dv, pwl + OFF_WD + l * FFNv * Dv,
            bV + l * Dv, pa, nullptr, nullptr, NTOK, Dv, FFNv, 0);

        ln_add<<<NTOK, 128>>>(pa, ln2g + l * Dv, ln2b + l * Dv, px);
    }

    gemm_tc<<<dim3(VOCABv / 128, NTOK / 128), 256, SM_TOTAL>>>(
        pxh, pxl, pwh + OFF_WO, pwl + OFF_WO, bout, out, nullptr, nullptr,
        NTOK, VOCABv, Dv, 0);
}